// round 12
// baseline (speedup 1.0000x reference)
#include <cuda_runtime.h>
#include <cuda_fp16.h>
#include <math.h>
#include <stdint.h>

// RegionOutputLayer via fp16 mma.sync (m16n8k16), compute_100-safe.
// R12: ks-level fragment software pipeline (b double-buffered, a reloaded
// post-consumption), A-halo load spread across 8 stages, merged prep.

namespace {
constexpr int COUT = 425;
constexpr int BATCH = 16, HH = 40, WW = 40;
constexpr int PW = 42, PPI = 42 * 42;      // 1764
constexpr int P = BATCH * PPI;             // 28224
constexpr int NSP = BATCH * HH * WW;       // 25600
constexpr int GPRE = 64;
constexpr int PROWS = GPRE + P + 128;      // 28416
constexpr int MTILES = 221;
constexpr int MROWS = MTILES * 128;        // 28288

constexpr int HALO = 216;                  // 128 + 2*44 pad
constexpr int ABYTES = HALO * 128;         // 27648
constexpr int ACH = HALO * 8;              // 1728 16B chunks
constexpr int BBYTES = 16384;
constexpr int SMEM1 = 2 * ABYTES + 3 * BBYTES;   // 104448

constexpr int TILE2 = 16384;
constexpr int STAGE2 = 2 * TILE2;
constexpr int SMEM2 = 3 * STAGE2;          // 98304

constexpr int DEC_STRIDE = 436;
constexpr int SMEM_DEC = 40 * DEC_STRIDE * 4;

constexpr int NT = 128;                    // 4 warps
}

__device__ __align__(128) __half g_xp[(size_t)PROWS * 512];
__device__ __align__(128) __half g_h [(size_t)MROWS * 512];
__device__ __align__(128) __half g_w1t[9 * 512 * 512];   // [tap][cout][cin]
__device__ __align__(128) __half g_w2t[512 * 512];
__device__ __align__(128) float  g_det[(size_t)MROWS * 512];
__device__ float g_s1[512], g_b1[512];

static __device__ __forceinline__ uint32_t s2u(const void* p) {
    uint32_t a;
    asm("{ .reg .u64 t; cvta.to.shared.u64 t, %1; cvt.u32.u64 %0, t; }" : "=r"(a) : "l"(p));
    return a;
}
static __device__ __forceinline__ void cpa16(uint32_t dst, const void* src) {
    asm volatile("cp.async.cg.shared.global [%0], [%1], 16;"
                 :: "r"(dst), "l"(__cvta_generic_to_global(src)));
}
#define CP_COMMIT() asm volatile("cp.async.commit_group;" ::: "memory")
#define CP_WAIT(n)  asm volatile("cp.async.wait_group %0;" :: "n"(n) : "memory")
#define LDSM4(r, a) \
    asm volatile("ldmatrix.sync.aligned.m8n8.x4.shared.b16 {%0,%1,%2,%3}, [%4];" \
                 : "=r"((r)[0]), "=r"((r)[1]), "=r"((r)[2]), "=r"((r)[3]) : "r"(a))
#define MMA16(c, a, b0, b1) \
    asm volatile("mma.sync.aligned.m16n8k16.row.col.f32.f16.f16.f32 " \
                 "{%0,%1,%2,%3},{%4,%5,%6,%7},{%8,%9},{%0,%1,%2,%3};" \
                 : "+f"((c)[0]), "+f"((c)[1]), "+f"((c)[2]), "+f"((c)[3]) \
                 : "r"((a)[0]), "r"((a)[1]), "r"((a)[2]), "r"((a)[3]), "r"(b0), "r"(b1))

// ------------------------------- prep (merged) ----------------------------
__global__ void prep_all(const float* __restrict__ x,
                         const float* __restrict__ w1, const float* __restrict__ w2,
                         const float* __restrict__ gamma, const float* __restrict__ beta,
                         const float* __restrict__ mean, const float* __restrict__ var) {
    int blk = blockIdx.x;
    if (blk < 5376) {                       // prep_x: (8 c-blocks, 42 rows, 16 imgs)
        __shared__ float s[64][41];
        int c0 = (blk & 7) * 64;
        int yp = (blk >> 3) % 42;
        int b  = blk / (8 * 42);
        int tid = threadIdx.x;
        int y = yp - 1;
        bool interior = (y >= 0 && y < HH);
        if (interior)
            for (int i = tid; i < 64 * 40; i += 256) {
                int c = i / 40, xx = i % 40;
                s[c][xx] = x[(((size_t)b * 512 + c0 + c) * HH + y) * WW + xx];
            }
        __syncthreads();
        size_t pbase = (size_t)GPRE + (size_t)b * PPI + (size_t)yp * PW;
        for (int i = tid; i < 42 * 64; i += 256) {
            int xp = i >> 6, c = i & 63;
            float v = (interior && xp >= 1 && xp <= 40) ? s[c][xp - 1] : 0.f;
            g_xp[(pbase + xp) * 512 + c0 + c] = __float2half_rn(v);
        }
    } else if (blk < 5632) {                // w1 transpose (256 blocks)
        __shared__ float s[9216];
        int r0 = (blk - 5376) * 1024;
        const float* src = w1 + (size_t)r0 * 9;
        for (int i = threadIdx.x; i < 9216; i += 256) s[i] = src[i];
        __syncthreads();
#pragma unroll
        for (int t = 0; t < 9; t++)
            for (int i = threadIdx.x; i < 1024; i += 256)
                g_w1t[(size_t)t * 262144 + r0 + i] = __float2half_rn(s[i * 9 + t]);
    } else if (blk < 5664) {                // w2 (32 blocks)
        int base = (blk - 5632) * 8192;
        for (int i = threadIdx.x; i < 8192; i += 256) {
            int idx = base + i;
            int co = idx >> 9, ci = idx & 511;
            g_w2t[idx] = __float2half_rn(co < COUT ? w2[co * 512 + ci] : 0.f);
        }
    } else {                                // BN fold
        for (int i = threadIdx.x; i < 512; i += 256) {
            float s = gamma[i] * rsqrtf(var[i] + 1e-5f);
            g_s1[i] = s;
            g_b1[i] = beta[i] - mean[i] * s;
        }
    }
}

// ------------------------------- conv1 -----------------------------------
__global__ void __launch_bounds__(NT, 2)
conv1_mma() {
    extern __shared__ __align__(128) __half smem[];
    const uint32_t sbase = s2u(smem);
    const int tid = threadIdx.x, lane = tid & 31, warp = tid >> 5;
    const int wm = (warp & 1) * 64;
    const int wn = (warp >> 1) * 64;
    const int n0 = blockIdx.x * 128;
    const int p0 = blockIdx.y * 128;

    float acc[4][8][4];
#pragma unroll
    for (int i = 0; i < 4; i++)
#pragma unroll
        for (int j = 0; j < 8; j++)
#pragma unroll
            for (int k = 0; k < 4; k++) acc[i][j][k] = 0.f;

    const __half* Abase = g_xp + (size_t)(GPRE + p0 - 44) * 512;

    auto LOAD_A_FULL = [&](int kc, int slot) {
        const __half* src = Abase + kc * 64;
        uint32_t dst = sbase + slot * ABYTES;
#pragma unroll
        for (int u = 0; u < 14; u++) {
            int id = tid + u * NT;
            if (id < ACH) {
                int r = id >> 3, c = id & 7;
                cpa16(dst + r * 128 + ((c ^ (r & 7)) * 16), src + (size_t)r * 512 + c * 8);
            }
        }
    };
    auto LOAD_A_PART = [&](int kc, int slot, int part) {   // 216 chunks per part
        const __half* src = Abase + kc * 64;
        uint32_t dst = sbase + slot * ABYTES;
        int id = part * 216 + tid;
        {
            int r = id >> 3, c = id & 7;
            cpa16(dst + r * 128 + ((c ^ (r & 7)) * 16), src + (size_t)r * 512 + c * 8);
        }
        if (tid < 88) {
            id += NT;
            int r = id >> 3, c = id & 7;
            cpa16(dst + r * 128 + ((c ^ (r & 7)) * 16), src + (size_t)r * 512 + c * 8);
        }
    };
    auto LOAD_B = [&](int kc, int tap, int slot) {
        const __half* src = g_w1t + ((size_t)tap * 512 + n0) * 512 + kc * 64;
        uint32_t dst = sbase + 2 * ABYTES + slot * BBYTES;
#pragma unroll
        for (int u = 0; u < 8; u++) {
            int id = tid + u * NT;
            int r = id >> 3, c = id & 7;
            cpa16(dst + r * 128 + ((c ^ (r & 7)) * 16), src + (size_t)r * 512 + c * 8);
        }
    };

    const int rA_base = wm + (lane & 15) + 44;
    const int hiA = lane >> 4;
    const int rB = wn + (lane & 7) + ((lane & 16) >> 1);
    const int hiB = (lane >> 3) & 1;

    auto COMPUTE = [&](uint32_t Ab, int shift, uint32_t Bb) {
        uint32_t a[4][4], b[2][4][4];
        // preload ks=0
#pragma unroll
        for (int i = 0; i < 4; i++) {
            int r = rA_base + 16 * i + shift;
            LDSM4(a[i], Ab + r * 128 + ((hiA ^ (r & 7)) * 16));
        }
#pragma unroll
        for (int pr = 0; pr < 4; pr++) {
            int r = rB + 16 * pr;
            LDSM4(b[0][pr], Bb + r * 128 + ((hiB ^ (r & 7)) * 16));
        }
#pragma unroll
        for (int ks = 0; ks < 4; ks++) {
            const int cur = ks & 1, nxt = cur ^ 1;
            if (ks < 3) {
#pragma unroll
                for (int pr = 0; pr < 4; pr++) {
                    int r = rB + 16 * pr;
                    LDSM4(b[nxt][pr], Bb + r * 128 + (((2 * (ks + 1) + hiB) ^ (r & 7)) * 16));
                }
            }
#pragma unroll
            for (int i = 0; i < 4; i++) {
#pragma unroll
                for (int j = 0; j < 8; j++)
                    MMA16(acc[i][j], a[i], b[cur][j >> 1][(j & 1) * 2],
                          b[cur][j >> 1][(j & 1) * 2 + 1]);
                if (ks < 3) {
                    int r = rA_base + 16 * i + shift;
                    LDSM4(a[i], Ab + r * 128 + (((2 * (ks + 1) + hiA) ^ (r & 7)) * 16));
                }
            }
        }
    };

    // prologue
    LOAD_A_FULL(0, 0); LOAD_B(0, 0, 0); CP_COMMIT();
    LOAD_B(0, 1, 1); CP_COMMIT();

    for (int kc = 0; kc < 8; kc++) {
        const uint32_t Ab = sbase + (kc & 1) * ABYTES;
#pragma unroll
        for (int tap = 0; tap < 9; tap++) {
            CP_WAIT(1);
            __syncthreads();
            if (tap + 2 < 9) {
                LOAD_B(kc, tap + 2, (tap + 2) % 3);
            } else if (kc < 7) {
                LOAD_B(kc + 1, tap + 2 - 9, (tap + 2) % 3);
            }
            if (tap < 8 && kc < 7) LOAD_A_PART(kc + 1, (kc + 1) & 1, tap);
            CP_COMMIT();
            const int shift = (tap / 3 - 1) * PW + (tap % 3) - 1;   // compile-time
            COMPUTE(Ab, shift, sbase + 2 * ABYTES + (tap % 3) * BBYTES);
        }
    }

    __syncthreads();
    float* ssc = reinterpret_cast<float*>(smem);
    float* ssh = ssc + 128;
    if (tid < 128) {
        int c = n0 + tid;
        ssc[tid] = g_s1[c];
        ssh[tid] = g_b1[c];
    }
    __syncthreads();

    const int g = lane >> 2, t = lane & 3;
#pragma unroll
    for (int i = 0; i < 4; i++) {
#pragma unroll
        for (int j = 0; j < 8; j++) {
            int cl = wn + 8 * j + 2 * t;
            int ch = n0 + cl;
#pragma unroll
            for (int hf = 0; hf < 2; hf++) {
                int row = p0 + wm + 16 * i + g + hf * 8;
                float v0 = acc[i][j][hf * 2 + 0];
                float v1 = acc[i][j][hf * 2 + 1];
                v0 = fmaf(v0, ssc[cl], ssh[cl]);
                v1 = fmaf(v1, ssc[cl + 1], ssh[cl + 1]);
                v0 = v0 / (1.f + __expf(-v0));
                v1 = v1 / (1.f + __expf(-v1));
                *reinterpret_cast<__half2*>(&g_h[(size_t)row * 512 + ch]) =
                    __floats2half2_rn(v0, v1);
            }
        }
    }
}

// ------------------------------- conv2 -----------------------------------
__global__ void __launch_bounds__(NT, 2)
conv2_mma(const float* __restrict__ bias2) {
    extern __shared__ __align__(128) __half smem[];
    const uint32_t sbase = s2u(smem);
    const int tid = threadIdx.x, lane = tid & 31, warp = tid >> 5;
    const int wm = (warp & 1) * 64;
    const int wn = (warp >> 1) * 64;
    const int n0 = blockIdx.x * 128;
    const int p0 = blockIdx.y * 128;

    float acc[4][8][4];
#pragma unroll
    for (int i = 0; i < 4; i++)
#pragma unroll
        for (int j = 0; j < 8; j++)
#pragma unroll
            for (int k = 0; k < 4; k++) acc[i][j][k] = 0.f;

    auto LOADSTAGE = [&](int s, int slot) {
        uint32_t dstA = sbase + slot * STAGE2;
        uint32_t dstB = dstA + TILE2;
        int kc = s * 64;
        const __half* srcA = g_h + (size_t)p0 * 512 + kc;
        const __half* srcB = g_w2t + (size_t)n0 * 512 + kc;
#pragma unroll
        for (int u = 0; u < 8; u++) {
            int q = tid + u * NT;
            int r = q >> 3, c = q & 7;
            cpa16(dstA + r * 128 + ((c ^ (r & 7)) * 16), srcA + (size_t)r * 512 + c * 8);
        }
#pragma unroll
        for (int u = 0; u < 8; u++) {
            int q = tid + u * NT;
            int r = q >> 3, c = q & 7;
            cpa16(dstB + r * 128 + ((c ^ (r & 7)) * 16), srcB + (size_t)r * 512 + c * 8);
        }
        CP_COMMIT();
    };

    const int rA = wm + (lane & 15);
    const int hiA = lane >> 4;
    const int rB = wn + (lane & 7) + ((lane & 16) >> 1);
    const int hiB = (lane >> 3) & 1;

    auto COMPUTE = [&](int slot) {
        uint32_t Ab = sbase + slot * STAGE2;
        uint32_t Bb = Ab + TILE2;
        uint32_t a[4][4], b[2][4][4];
#pragma unroll
        for (int i = 0; i < 4; i++) {
            int r = rA + 16 * i;
            LDSM4(a[i], Ab + r * 128 + ((hiA ^ (r & 7)) * 16));
        }
#pragma unroll
        for (int pr = 0; pr < 4; pr++) {
            int r = rB + 16 * pr;
            LDSM4(b[0][pr], Bb + r * 128 + ((hiB ^ (r & 7)) * 16));
        }
#pragma unroll
        for (int ks = 0; ks < 4; ks++) {
            const int cur = ks & 1, nxt = cur ^ 1;
            if (ks < 3) {
#pragma unroll
                for (int pr = 0; pr < 4; pr++) {
                    int r = rB + 16 * pr;
                    LDSM4(b[nxt][pr], Bb + r * 128 + (((2 * (ks + 1) + hiB) ^ (r & 7)) * 16));
                }
            }
#pragma unroll
            for (int i = 0; i < 4; i++) {
#pragma unroll
                for (int j = 0; j < 8; j++)
                    MMA16(acc[i][j], a[i], b[cur][j >> 1][(j & 1) * 2],
                          b[cur][j >> 1][(j & 1) * 2 + 1]);
                if (ks < 3) {
                    int r = rA + 16 * i;
                    LDSM4(a[i], Ab + r * 128 + (((2 * (ks + 1) + hiA) ^ (r & 7)) * 16));
                }
            }
        }
    };

    LOADSTAGE(0, 0);
    LOADSTAGE(1, 1);
#pragma unroll
    for (int s = 0; s < 8; s++) {
        if (s + 2 < 8) CP_WAIT(1); else CP_WAIT(0);
        __syncthreads();
        if (s + 2 < 8) LOADSTAGE(s + 2, (s + 2) % 3);
        COMPUTE(s % 3);
    }

    __syncthreads();
    float* ssh = reinterpret_cast<float*>(smem);
    if (tid < 128) {
        int c = n0 + tid;
        ssh[tid] = (c < COUT) ? bias2[c] : 0.f;
    }
    __syncthreads();

    const int g = lane >> 2, t = lane & 3;
#pragma unroll
    for (int i = 0; i < 4; i++) {
#pragma unroll
        for (int j = 0; j < 8; j++) {
            int cl = wn + 8 * j + 2 * t;
            int ch = n0 + cl;
#pragma unroll
            for (int hf = 0; hf < 2; hf++) {
                int row = p0 + wm + 16 * i + g + hf * 8;
                *reinterpret_cast<float2*>(&g_det[(size_t)row * 512 + ch]) =
                    make_float2(acc[i][j][hf * 2 + 0] + ssh[cl],
                                acc[i][j][hf * 2 + 1] + ssh[cl + 1]);
            }
        }
    }
}

// ------------------------------- decode ----------------------------------
__global__ void decode_kernel(const float* __restrict__ anchors, float* __restrict__ out) {
    extern __shared__ float srow[];            // [40][DEC_STRIDE]
    int y = blockIdx.x, b = blockIdx.y;
    int tid = threadIdx.x;

    const float* rowbase = g_det + ((size_t)b * PPI + (size_t)(y + 1) * PW + 1) * 512;
    for (int i = tid; i < 40 * 107; i += 256) {
        int xl = i / 107, q = i - xl * 107;
        *reinterpret_cast<float4*>(&srow[xl * DEC_STRIDE + q * 4]) =
            *reinterpret_cast<const float4*>(rowbase + (size_t)xl * 512 + q * 4);
    }
    __syncthreads();

    if (tid < 200) {
        int xl = tid / 5, a = tid - xl * 5;
        const float* dp = srow + xl * DEC_STRIDE + a * 85;
        float d0 = dp[0], d1 = dp[1], d2 = dp[2], d3 = dp[3], d4 = dp[4];
        float cls[80], mx = -1e30f;
#pragma unroll
        for (int c = 0; c < 80; c++) { cls[c] = dp[5 + c]; mx = fmaxf(mx, cls[c]); }
        float sum = 0.f;
#pragma unroll
        for (int c = 0; c < 80; c++) { cls[c] = __expf(cls[c] - mx); sum += cls[c]; }
        float inv = 1.f / sum;

        int n = b * 1600 + y * 40 + xl;
        float bx = ((float)xl + 1.f / (1.f + __expf(-d0))) * (1.f / 40.f);
        float by = ((float)y + 1.f / (1.f + __expf(-d1))) * (1.f / 40.f);
        float bw = __ldg(anchors + 2 * a)     * __expf(d2);
        float bh = __ldg(anchors + 2 * a + 1) * __expf(d3);

        *reinterpret_cast<float4*>(&out[(size_t)(n * 5 + a) * 4]) = make_float4(bx, by, bw, bh);
        out[512000 + n * 5 + a] = 1.f / (1.f + __expf(-d4));
        float* co = out + 640000 + (size_t)(n * 5 + a) * 80;
#pragma unroll
        for (int c = 0; c < 80; c += 4)
            *reinterpret_cast<float4*>(&co[c]) = make_float4(cls[c] * inv, cls[c + 1] * inv,
                                                             cls[c + 2] * inv, cls[c + 3] * inv);
    }
}

// ------------------------------- host ------------------------------------
extern "C" void kernel_launch(void* const* d_in, const int* in_sizes, int n_in,
                              void* d_out, int out_size) {
    const float* x       = (const float*)d_in[0];
    const float* w1      = (const float*)d_in[1];
    const float* gamma   = (const float*)d_in[2];
    const float* beta    = (const float*)d_in[3];
    const float* mean    = (const float*)d_in[4];
    const float* var     = (const float*)d_in[5];
    const float* w2      = (const float*)d_in[6];
    const float* b2      = (const float*)d_in[7];
    const float* anchors = (const float*)d_in[8];
    float* out = (float*)d_out;

    cudaFuncSetAttribute(conv1_mma,     cudaFuncAttributeMaxDynamicSharedMemorySize, SMEM1);
    cudaFuncSetAttribute(conv2_mma,     cudaFuncAttributeMaxDynamicSharedMemorySize, SMEM2);
    cudaFuncSetAttribute(decode_kernel, cudaFuncAttributeMaxDynamicSharedMemorySize, SMEM_DEC);

    prep_all<<<5665, 256>>>(x, w1, w2, gamma, beta, mean, var);
    conv1_mma<<<dim3(4, MTILES), NT, SMEM1>>>();
    conv2_mma<<<dim3(4, MTILES), NT, SMEM2>>>(b2);
    decode_kernel<<<dim3(40, 16), 256, SMEM_DEC>>>(anchors, out);
}

// round 13
// speedup vs baseline: 1.0390x; 1.0390x over previous
#include <cuda_runtime.h>
#include <cuda_fp16.h>
#include <math.h>
#include <stdint.h>

// RegionOutputLayer via fp16 mma.sync (m16n8k16), compute_100-safe.
// R13: conv kernels = R11 (best, 422us). Decode rebuilt: 2 threads per
// (x,anchor), cls[40] per thread (no local spills), shfl pair-reduction.

namespace {
constexpr int COUT = 425;
constexpr int BATCH = 16, HH = 40, WW = 40;
constexpr int PW = 42, PPI = 42 * 42;      // 1764
constexpr int P = BATCH * PPI;             // 28224
constexpr int NSP = BATCH * HH * WW;       // 25600
constexpr int GPRE = 64;
constexpr int PROWS = GPRE + P + 128;      // 28416
constexpr int MTILES = 221;
constexpr int MROWS = MTILES * 128;        // 28288

constexpr int HALO = 216;                  // 128 + 2*44 pad
constexpr int ABYTES = HALO * 128;         // 27648
constexpr int ACH = HALO * 8;              // 1728 16B chunks
constexpr int BBYTES = 16384;
constexpr int SMEM1 = 2 * ABYTES + 3 * BBYTES;   // 104448

constexpr int TILE2 = 16384;
constexpr int STAGE2 = 2 * TILE2;
constexpr int SMEM2 = 3 * STAGE2;          // 98304

constexpr int DEC_STRIDE = 436;
constexpr int SMEM_DEC = 40 * DEC_STRIDE * 4;    // 69760

constexpr int NT = 128;                    // 4 warps
}

__device__ __align__(128) __half g_xp[(size_t)PROWS * 512];
__device__ __align__(128) __half g_h [(size_t)MROWS * 512];
__device__ __align__(128) __half g_w1t[9 * 512 * 512];   // [tap][cout][cin]
__device__ __align__(128) __half g_w2t[512 * 512];
__device__ __align__(128) float  g_det[(size_t)MROWS * 512];
__device__ float g_s1[512], g_b1[512];

static __device__ __forceinline__ uint32_t s2u(const void* p) {
    uint32_t a;
    asm("{ .reg .u64 t; cvta.to.shared.u64 t, %1; cvt.u32.u64 %0, t; }" : "=r"(a) : "l"(p));
    return a;
}
static __device__ __forceinline__ void cpa16(uint32_t dst, const void* src) {
    asm volatile("cp.async.cg.shared.global [%0], [%1], 16;"
                 :: "r"(dst), "l"(__cvta_generic_to_global(src)));
}
#define CP_COMMIT() asm volatile("cp.async.commit_group;" ::: "memory")
#define CP_WAIT(n)  asm volatile("cp.async.wait_group %0;" :: "n"(n) : "memory")
#define LDSM4(r, a) \
    asm volatile("ldmatrix.sync.aligned.m8n8.x4.shared.b16 {%0,%1,%2,%3}, [%4];" \
                 : "=r"((r)[0]), "=r"((r)[1]), "=r"((r)[2]), "=r"((r)[3]) : "r"(a))
#define MMA16(c, a, b0, b1) \
    asm volatile("mma.sync.aligned.m16n8k16.row.col.f32.f16.f16.f32 " \
                 "{%0,%1,%2,%3},{%4,%5,%6,%7},{%8,%9},{%0,%1,%2,%3};" \
                 : "+f"((c)[0]), "+f"((c)[1]), "+f"((c)[2]), "+f"((c)[3]) \
                 : "r"((a)[0]), "r"((a)[1]), "r"((a)[2]), "r"((a)[3]), "r"(b0), "r"(b1))

// ------------------------------- prep (merged) ----------------------------
__global__ void prep_all(const float* __restrict__ x,
                         const float* __restrict__ w1, const float* __restrict__ w2,
                         const float* __restrict__ gamma, const float* __restrict__ beta,
                         const float* __restrict__ mean, const float* __restrict__ var) {
    int blk = blockIdx.x;
    if (blk < 5376) {                       // prep_x: (8 c-blocks, 42 rows, 16 imgs)
        __shared__ float s[64][41];
        int c0 = (blk & 7) * 64;
        int yp = (blk >> 3) % 42;
        int b  = blk / (8 * 42);
        int tid = threadIdx.x;
        int y = yp - 1;
        bool interior = (y >= 0 && y < HH);
        if (interior)
            for (int i = tid; i < 64 * 40; i += 256) {
                int c = i / 40, xx = i % 40;
                s[c][xx] = x[(((size_t)b * 512 + c0 + c) * HH + y) * WW + xx];
            }
        __syncthreads();
        size_t pbase = (size_t)GPRE + (size_t)b * PPI + (size_t)yp * PW;
        for (int i = tid; i < 42 * 64; i += 256) {
            int xp = i >> 6, c = i & 63;
            float v = (interior && xp >= 1 && xp <= 40) ? s[c][xp - 1] : 0.f;
            g_xp[(pbase + xp) * 512 + c0 + c] = __float2half_rn(v);
        }
    } else if (blk < 5632) {                // w1 transpose (256 blocks)
        __shared__ float s[9216];
        int r0 = (blk - 5376) * 1024;
        const float* src = w1 + (size_t)r0 * 9;
        for (int i = threadIdx.x; i < 9216; i += 256) s[i] = src[i];
        __syncthreads();
#pragma unroll
        for (int t = 0; t < 9; t++)
            for (int i = threadIdx.x; i < 1024; i += 256)
                g_w1t[(size_t)t * 262144 + r0 + i] = __float2half_rn(s[i * 9 + t]);
    } else if (blk < 5664) {                // w2 (32 blocks)
        int base = (blk - 5632) * 8192;
        for (int i = threadIdx.x; i < 8192; i += 256) {
            int idx = base + i;
            int co = idx >> 9, ci = idx & 511;
            g_w2t[idx] = __float2half_rn(co < COUT ? w2[co * 512 + ci] : 0.f);
        }
    } else {                                // BN fold
        for (int i = threadIdx.x; i < 512; i += 256) {
            float s = gamma[i] * rsqrtf(var[i] + 1e-5f);
            g_s1[i] = s;
            g_b1[i] = beta[i] - mean[i] * s;
        }
    }
}

// ------------------------------- conv1 (R11) ------------------------------
__global__ void __launch_bounds__(NT, 2)
conv1_mma() {
    extern __shared__ __align__(128) __half smem[];
    const uint32_t sbase = s2u(smem);
    const int tid = threadIdx.x, lane = tid & 31, warp = tid >> 5;
    const int wm = (warp & 1) * 64;
    const int wn = (warp >> 1) * 64;
    const int n0 = blockIdx.x * 128;
    const int p0 = blockIdx.y * 128;

    float acc[4][8][4];
#pragma unroll
    for (int i = 0; i < 4; i++)
#pragma unroll
        for (int j = 0; j < 8; j++)
#pragma unroll
            for (int k = 0; k < 4; k++) acc[i][j][k] = 0.f;

    const __half* Abase = g_xp + (size_t)(GPRE + p0 - 44) * 512;

    auto LOAD_A = [&](int kc, int slot) {
        const __half* src = Abase + kc * 64;
        uint32_t dst = sbase + slot * ABYTES;
#pragma unroll
        for (int u = 0; u < 14; u++) {
            int id = tid + u * NT;
            if (id < ACH) {
                int r = id >> 3, c = id & 7;
                cpa16(dst + r * 128 + ((c ^ (r & 7)) * 16), src + (size_t)r * 512 + c * 8);
            }
        }
    };
    auto LOAD_B = [&](int kc, int tap, int slot) {
        const __half* src = g_w1t + ((size_t)tap * 512 + n0) * 512 + kc * 64;
        uint32_t dst = sbase + 2 * ABYTES + slot * BBYTES;
#pragma unroll
        for (int u = 0; u < 8; u++) {
            int id = tid + u * NT;
            int r = id >> 3, c = id & 7;
            cpa16(dst + r * 128 + ((c ^ (r & 7)) * 16), src + (size_t)r * 512 + c * 8);
        }
    };

    const int rA_base = wm + (lane & 15) + 44;
    const int hiA = lane >> 4;
    const int rB = wn + (lane & 7) + ((lane & 16) >> 1);
    const int hiB = (lane >> 3) & 1;

    auto COMPUTE = [&](uint32_t Ab, int shift, uint32_t Bb) {
#pragma unroll
        for (int ks = 0; ks < 4; ks++) {
            uint32_t a[4][4], b[4][4];
#pragma unroll
            for (int i = 0; i < 4; i++) {
                int r = rA_base + 16 * i + shift;
                LDSM4(a[i], Ab + r * 128 + (((2 * ks + hiA) ^ (r & 7)) * 16));
            }
#pragma unroll
            for (int pr = 0; pr < 4; pr++) {
                int r = rB + 16 * pr;
                LDSM4(b[pr], Bb + r * 128 + (((2 * ks + hiB) ^ (r & 7)) * 16));
            }
#pragma unroll
            for (int i = 0; i < 4; i++)
#pragma unroll
                for (int j = 0; j < 8; j++)
                    MMA16(acc[i][j], a[i], b[j >> 1][(j & 1) * 2], b[j >> 1][(j & 1) * 2 + 1]);
        }
    };

    LOAD_A(0, 0); LOAD_B(0, 0, 0); CP_COMMIT();
    LOAD_B(0, 1, 1); CP_COMMIT();

    for (int kc = 0; kc < 8; kc++) {
        const uint32_t Ab = sbase + (kc & 1) * ABYTES;
#pragma unroll
        for (int tap = 0; tap < 9; tap++) {
            CP_WAIT(1);
            __syncthreads();
            if (tap + 2 < 9) {
                LOAD_B(kc, tap + 2, (tap + 2) % 3);
            } else if (kc < 7) {
                LOAD_B(kc + 1, tap + 2 - 9, (tap + 2) % 3);
            }
            if (tap == 0 && kc < 7) LOAD_A(kc + 1, (kc + 1) & 1);
            CP_COMMIT();
            const int shift = (tap / 3 - 1) * PW + (tap % 3) - 1;   // compile-time
            COMPUTE(Ab, shift, sbase + 2 * ABYTES + (tap % 3) * BBYTES);
        }
    }

    __syncthreads();
    float* ssc = reinterpret_cast<float*>(smem);
    float* ssh = ssc + 128;
    if (tid < 128) {
        int c = n0 + tid;
        ssc[tid] = g_s1[c];
        ssh[tid] = g_b1[c];
    }
    __syncthreads();

    const int g = lane >> 2, t = lane & 3;
#pragma unroll
    for (int i = 0; i < 4; i++) {
#pragma unroll
        for (int j = 0; j < 8; j++) {
            int cl = wn + 8 * j + 2 * t;
            int ch = n0 + cl;
#pragma unroll
            for (int hf = 0; hf < 2; hf++) {
                int row = p0 + wm + 16 * i + g + hf * 8;
                float v0 = acc[i][j][hf * 2 + 0];
                float v1 = acc[i][j][hf * 2 + 1];
                v0 = fmaf(v0, ssc[cl], ssh[cl]);
                v1 = fmaf(v1, ssc[cl + 1], ssh[cl + 1]);
                v0 = v0 / (1.f + __expf(-v0));
                v1 = v1 / (1.f + __expf(-v1));
                *reinterpret_cast<__half2*>(&g_h[(size_t)row * 512 + ch]) =
                    __floats2half2_rn(v0, v1);
            }
        }
    }
}

// ------------------------------- conv2 (R11) ------------------------------
__global__ void __launch_bounds__(NT, 2)
conv2_mma(const float* __restrict__ bias2) {
    extern __shared__ __align__(128) __half smem[];
    const uint32_t sbase = s2u(smem);
    const int tid = threadIdx.x, lane = tid & 31, warp = tid >> 5;
    const int wm = (warp & 1) * 64;
    const int wn = (warp >> 1) * 64;
    const int n0 = blockIdx.x * 128;
    const int p0 = blockIdx.y * 128;

    float acc[4][8][4];
#pragma unroll
    for (int i = 0; i < 4; i++)
#pragma unroll
        for (int j = 0; j < 8; j++)
#pragma unroll
            for (int k = 0; k < 4; k++) acc[i][j][k] = 0.f;

    auto LOADSTAGE = [&](int s, int slot) {
        uint32_t dstA = sbase + slot * STAGE2;
        uint32_t dstB = dstA + TILE2;
        int kc = s * 64;
        const __half* srcA = g_h + (size_t)p0 * 512 + kc;
        const __half* srcB = g_w2t + (size_t)n0 * 512 + kc;
#pragma unroll
        for (int u = 0; u < 8; u++) {
            int q = tid + u * NT;
            int r = q >> 3, c = q & 7;
            cpa16(dstA + r * 128 + ((c ^ (r & 7)) * 16), srcA + (size_t)r * 512 + c * 8);
        }
#pragma unroll
        for (int u = 0; u < 8; u++) {
            int q = tid + u * NT;
            int r = q >> 3, c = q & 7;
            cpa16(dstB + r * 128 + ((c ^ (r & 7)) * 16), srcB + (size_t)r * 512 + c * 8);
        }
        CP_COMMIT();
    };

    const int rA = wm + (lane & 15);
    const int hiA = lane >> 4;
    const int rB = wn + (lane & 7) + ((lane & 16) >> 1);
    const int hiB = (lane >> 3) & 1;

    auto COMPUTE = [&](int slot) {
        uint32_t Ab = sbase + slot * STAGE2;
        uint32_t Bb = Ab + TILE2;
#pragma unroll
        for (int ks = 0; ks < 4; ks++) {
            uint32_t a[4][4], b[4][4];
#pragma unroll
            for (int i = 0; i < 4; i++) {
                int r = rA + 16 * i;
                LDSM4(a[i], Ab + r * 128 + (((2 * ks + hiA) ^ (r & 7)) * 16));
            }
#pragma unroll
            for (int pr = 0; pr < 4; pr++) {
                int r = rB + 16 * pr;
                LDSM4(b[pr], Bb + r * 128 + (((2 * ks + hiB) ^ (r & 7)) * 16));
            }
#pragma unroll
            for (int i = 0; i < 4; i++)
#pragma unroll
                for (int j = 0; j < 8; j++)
                    MMA16(acc[i][j], a[i], b[j >> 1][(j & 1) * 2], b[j >> 1][(j & 1) * 2 + 1]);
        }
    };

    LOADSTAGE(0, 0);
    LOADSTAGE(1, 1);
#pragma unroll
    for (int s = 0; s < 8; s++) {
        if (s + 2 < 8) CP_WAIT(1); else CP_WAIT(0);
        __syncthreads();
        if (s + 2 < 8) LOADSTAGE(s + 2, (s + 2) % 3);
        COMPUTE(s % 3);
    }

    __syncthreads();
    float* ssh = reinterpret_cast<float*>(smem);
    if (tid < 128) {
        int c = n0 + tid;
        ssh[tid] = (c < COUT) ? bias2[c] : 0.f;
    }
    __syncthreads();

    const int g = lane >> 2, t = lane & 3;
#pragma unroll
    for (int i = 0; i < 4; i++) {
#pragma unroll
        for (int j = 0; j < 8; j++) {
            int cl = wn + 8 * j + 2 * t;
            int ch = n0 + cl;
#pragma unroll
            for (int hf = 0; hf < 2; hf++) {
                int row = p0 + wm + 16 * i + g + hf * 8;
                *reinterpret_cast<float2*>(&g_det[(size_t)row * 512 + ch]) =
                    make_float2(acc[i][j][hf * 2 + 0] + ssh[cl],
                                acc[i][j][hf * 2 + 1] + ssh[cl + 1]);
            }
        }
    }
}

// ------------------------------- decode (rebuilt) -------------------------
__global__ void __launch_bounds__(512)
decode_kernel(const float* __restrict__ anchors, float* __restrict__ out) {
    extern __shared__ float srow[];            // [40][DEC_STRIDE]
    int y = blockIdx.x, b = blockIdx.y;
    int tid = threadIdx.x;

    const float* rowbase = g_det + ((size_t)b * PPI + (size_t)(y + 1) * PW + 1) * 512;
    for (int i = tid; i < 40 * 107; i += 512) {
        int xl = i / 107, q = i - xl * 107;
        *reinterpret_cast<float4*>(&srow[xl * DEC_STRIDE + q * 4]) =
            *reinterpret_cast<const float4*>(rowbase + (size_t)xl * 512 + q * 4);
    }
    __syncthreads();

    // 2 threads per (x, anchor): pid = tid>>1 in [0,200), half = tid&1.
    // All threads execute the shfl path (clamped pid) so the full mask is legal.
    int pid = tid >> 1;
    int cpid = pid < 200 ? pid : 199;
    int half = tid & 1;
    int xl = cpid / 5, a = cpid - xl * 5;
    const float* dp = srow + xl * DEC_STRIDE + a * 85;

    float cls[40];
    float mx = -1e30f;
    const float* cp = dp + 5 + half * 40;
#pragma unroll
    for (int c = 0; c < 40; c++) { cls[c] = cp[c]; mx = fmaxf(mx, cls[c]); }
    mx = fmaxf(mx, __shfl_xor_sync(0xFFFFFFFF, mx, 1));
    float sum = 0.f;
#pragma unroll
    for (int c = 0; c < 40; c++) { cls[c] = __expf(cls[c] - mx); sum += cls[c]; }
    sum += __shfl_xor_sync(0xFFFFFFFF, sum, 1);
    float inv = 1.f / sum;

    if (pid < 200) {
        int n = b * 1600 + y * 40 + xl;
        float* co = out + 640000 + (size_t)(n * 5 + a) * 80 + half * 40;
#pragma unroll
        for (int c = 0; c < 40; c += 4)
            *reinterpret_cast<float4*>(&co[c]) = make_float4(cls[c] * inv, cls[c + 1] * inv,
                                                             cls[c + 2] * inv, cls[c + 3] * inv);
        if (half == 0) {
            float d0 = dp[0], d1 = dp[1], d2 = dp[2], d3 = dp[3], d4 = dp[4];
            float bx = ((float)xl + 1.f / (1.f + __expf(-d0))) * (1.f / 40.f);
            float by = ((float)y + 1.f / (1.f + __expf(-d1))) * (1.f / 40.f);
            float bw = __ldg(anchors + 2 * a)     * __expf(d2);
            float bh = __ldg(anchors + 2 * a + 1) * __expf(d3);
            *reinterpret_cast<float4*>(&out[(size_t)(n * 5 + a) * 4]) =
                make_float4(bx, by, bw, bh);
            out[512000 + n * 5 + a] = 1.f / (1.f + __expf(-d4));
        }
    }
}

// ------------------------------- host ------------------------------------
extern "C" void kernel_launch(void* const* d_in, const int* in_sizes, int n_in,
                              void* d_out, int out_size) {
    const float* x       = (const float*)d_in[0];
    const float* w1      = (const float*)d_in[1];
    const float* gamma   = (const float*)d_in[2];
    const float* beta    = (const float*)d_in[3];
    const float* mean    = (const float*)d_in[4];
    const float* var     = (const float*)d_in[5];
    const float* w2      = (const float*)d_in[6];
    const float* b2      = (const float*)d_in[7];
    const float* anchors = (const float*)d_in[8];
    float* out = (float*)d_out;

    cudaFuncSetAttribute(conv1_mma,     cudaFuncAttributeMaxDynamicSharedMemorySize, SMEM1);
    cudaFuncSetAttribute(conv2_mma,     cudaFuncAttributeMaxDynamicSharedMemorySize, SMEM2);
    cudaFuncSetAttribute(decode_kernel, cudaFuncAttributeMaxDynamicSharedMemorySize, SMEM_DEC);

    prep_all<<<5665, 256>>>(x, w1, w2, gamma, beta, mean, var);
    conv1_mma<<<dim3(4, MTILES), NT, SMEM1>>>();
    conv2_mma<<<dim3(4, MTILES), NT, SMEM2>>>(b2);
    decode_kernel<<<dim3(40, 16), 512, SMEM_DEC>>>(anchors, out);
}

// round 14
// speedup vs baseline: 1.0671x; 1.0270x over previous
#include <cuda_runtime.h>
#include <cuda_fp16.h>
#include <math.h>
#include <stdint.h>

// RegionOutputLayer via fp16 mma.sync (m16n8k16), compute_100-safe.
// R14: best-of-all-parts. Separate prep_w/prep_x (R11 — merged prep's 36KB
// static smem union killed prep_x occupancy), conv1/conv2 = R11 (422us),
// decode = R13 (2 thr/(x,anchor), no spills). conv2 stores trimmed to ch<428.

namespace {
constexpr int COUT = 425;
constexpr int BATCH = 16, HH = 40, WW = 40;
constexpr int PW = 42, PPI = 42 * 42;      // 1764
constexpr int P = BATCH * PPI;             // 28224
constexpr int NSP = BATCH * HH * WW;       // 25600
constexpr int GPRE = 64;
constexpr int PROWS = GPRE + P + 128;      // 28416
constexpr int MTILES = 221;
constexpr int MROWS = MTILES * 128;        // 28288

constexpr int HALO = 216;                  // 128 + 2*44 pad
constexpr int ABYTES = HALO * 128;         // 27648
constexpr int ACH = HALO * 8;              // 1728 16B chunks
constexpr int BBYTES = 16384;
constexpr int SMEM1 = 2 * ABYTES + 3 * BBYTES;   // 104448

constexpr int TILE2 = 16384;
constexpr int STAGE2 = 2 * TILE2;
constexpr int SMEM2 = 3 * STAGE2;          // 98304

constexpr int DEC_STRIDE = 436;
constexpr int SMEM_DEC = 40 * DEC_STRIDE * 4;    // 69760

constexpr int NT = 128;                    // 4 warps
}

__device__ __align__(128) __half g_xp[(size_t)PROWS * 512];
__device__ __align__(128) __half g_h [(size_t)MROWS * 512];
__device__ __align__(128) __half g_w1t[9 * 512 * 512];   // [tap][cout][cin]
__device__ __align__(128) __half g_w2t[512 * 512];
__device__ __align__(128) float  g_det[(size_t)MROWS * 512];
__device__ float g_s1[512], g_b1[512];

static __device__ __forceinline__ uint32_t s2u(const void* p) {
    uint32_t a;
    asm("{ .reg .u64 t; cvta.to.shared.u64 t, %1; cvt.u32.u64 %0, t; }" : "=r"(a) : "l"(p));
    return a;
}
static __device__ __forceinline__ void cpa16(uint32_t dst, const void* src) {
    asm volatile("cp.async.cg.shared.global [%0], [%1], 16;"
                 :: "r"(dst), "l"(__cvta_generic_to_global(src)));
}
#define CP_COMMIT() asm volatile("cp.async.commit_group;" ::: "memory")
#define CP_WAIT(n)  asm volatile("cp.async.wait_group %0;" :: "n"(n) : "memory")
#define LDSM4(r, a) \
    asm volatile("ldmatrix.sync.aligned.m8n8.x4.shared.b16 {%0,%1,%2,%3}, [%4];" \
                 : "=r"((r)[0]), "=r"((r)[1]), "=r"((r)[2]), "=r"((r)[3]) : "r"(a))
#define MMA16(c, a, b0, b1) \
    asm volatile("mma.sync.aligned.m16n8k16.row.col.f32.f16.f16.f32 " \
                 "{%0,%1,%2,%3},{%4,%5,%6,%7},{%8,%9},{%0,%1,%2,%3};" \
                 : "+f"((c)[0]), "+f"((c)[1]), "+f"((c)[2]), "+f"((c)[3]) \
                 : "r"((a)[0]), "r"((a)[1]), "r"((a)[2]), "r"((a)[3]), "r"(b0), "r"(b1))

// ------------------------------- prep ------------------------------------
__global__ void prep_w(const float* __restrict__ w1, const float* __restrict__ w2,
                       const float* __restrict__ gamma, const float* __restrict__ beta,
                       const float* __restrict__ mean, const float* __restrict__ var) {
    int blk = blockIdx.x;
    if (blk < 256) {                        // w1 transpose, both sides coalesced
        __shared__ float s[9216];
        int r0 = blk * 1024;
        const float* src = w1 + (size_t)r0 * 9;
        for (int i = threadIdx.x; i < 9216; i += 256) s[i] = src[i];
        __syncthreads();
#pragma unroll
        for (int t = 0; t < 9; t++)
            for (int i = threadIdx.x; i < 1024; i += 256)
                g_w1t[(size_t)t * 262144 + r0 + i] = __float2half_rn(s[i * 9 + t]);
    } else if (blk < 288) {
        int base = (blk - 256) * 8192;
        for (int i = threadIdx.x; i < 8192; i += 256) {
            int idx = base + i;
            int co = idx >> 9, ci = idx & 511;
            g_w2t[idx] = __float2half_rn(co < COUT ? w2[co * 512 + ci] : 0.f);
        }
    } else {
        for (int i = threadIdx.x; i < 512; i += 256) {
            float s = gamma[i] * rsqrtf(var[i] + 1e-5f);
            g_s1[i] = s;
            g_b1[i] = beta[i] - mean[i] * s;
        }
    }
}

__global__ void prep_x(const float* __restrict__ x) {
    __shared__ float s[64][41];
    int c0 = blockIdx.x * 64, yp = blockIdx.y, b = blockIdx.z;
    int tid = threadIdx.x;
    int y = yp - 1;
    bool interior = (y >= 0 && y < HH);
    if (interior)
        for (int i = tid; i < 64 * 40; i += 256) {
            int c = i / 40, xx = i % 40;
            s[c][xx] = x[(((size_t)b * 512 + c0 + c) * HH + y) * WW + xx];
        }
    __syncthreads();
    size_t pbase = (size_t)GPRE + (size_t)b * PPI + (size_t)yp * PW;
    for (int i = tid; i < 42 * 64; i += 256) {
        int xp = i >> 6, c = i & 63;
        float v = (interior && xp >= 1 && xp <= 40) ? s[c][xp - 1] : 0.f;
        g_xp[(pbase + xp) * 512 + c0 + c] = __float2half_rn(v);
    }
}

// ------------------------------- conv1 (R11) ------------------------------
__global__ void __launch_bounds__(NT, 2)
conv1_mma() {
    extern __shared__ __align__(128) __half smem[];
    const uint32_t sbase = s2u(smem);
    const int tid = threadIdx.x, lane = tid & 31, warp = tid >> 5;
    const int wm = (warp & 1) * 64;
    const int wn = (warp >> 1) * 64;
    const int n0 = blockIdx.x * 128;
    const int p0 = blockIdx.y * 128;

    float acc[4][8][4];
#pragma unroll
    for (int i = 0; i < 4; i++)
#pragma unroll
        for (int j = 0; j < 8; j++)
#pragma unroll
            for (int k = 0; k < 4; k++) acc[i][j][k] = 0.f;

    const __half* Abase = g_xp + (size_t)(GPRE + p0 - 44) * 512;

    auto LOAD_A = [&](int kc, int slot) {
        const __half* src = Abase + kc * 64;
        uint32_t dst = sbase + slot * ABYTES;
#pragma unroll
        for (int u = 0; u < 14; u++) {
            int id = tid + u * NT;
            if (id < ACH) {
                int r = id >> 3, c = id & 7;
                cpa16(dst + r * 128 + ((c ^ (r & 7)) * 16), src + (size_t)r * 512 + c * 8);
            }
        }
    };
    auto LOAD_B = [&](int kc, int tap, int slot) {
        const __half* src = g_w1t + ((size_t)tap * 512 + n0) * 512 + kc * 64;
        uint32_t dst = sbase + 2 * ABYTES + slot * BBYTES;
#pragma unroll
        for (int u = 0; u < 8; u++) {
            int id = tid + u * NT;
            int r = id >> 3, c = id & 7;
            cpa16(dst + r * 128 + ((c ^ (r & 7)) * 16), src + (size_t)r * 512 + c * 8);
        }
    };

    const int rA_base = wm + (lane & 15) + 44;
    const int hiA = lane >> 4;
    const int rB = wn + (lane & 7) + ((lane & 16) >> 1);
    const int hiB = (lane >> 3) & 1;

    auto COMPUTE = [&](uint32_t Ab, int shift, uint32_t Bb) {
#pragma unroll
        for (int ks = 0; ks < 4; ks++) {
            uint32_t a[4][4], b[4][4];
#pragma unroll
            for (int i = 0; i < 4; i++) {
                int r = rA_base + 16 * i + shift;
                LDSM4(a[i], Ab + r * 128 + (((2 * ks + hiA) ^ (r & 7)) * 16));
            }
#pragma unroll
            for (int pr = 0; pr < 4; pr++) {
                int r = rB + 16 * pr;
                LDSM4(b[pr], Bb + r * 128 + (((2 * ks + hiB) ^ (r & 7)) * 16));
            }
#pragma unroll
            for (int i = 0; i < 4; i++)
#pragma unroll
                for (int j = 0; j < 8; j++)
                    MMA16(acc[i][j], a[i], b[j >> 1][(j & 1) * 2], b[j >> 1][(j & 1) * 2 + 1]);
        }
    };

    LOAD_A(0, 0); LOAD_B(0, 0, 0); CP_COMMIT();
    LOAD_B(0, 1, 1); CP_COMMIT();

    for (int kc = 0; kc < 8; kc++) {
        const uint32_t Ab = sbase + (kc & 1) * ABYTES;
#pragma unroll
        for (int tap = 0; tap < 9; tap++) {
            CP_WAIT(1);
            __syncthreads();
            if (tap + 2 < 9) {
                LOAD_B(kc, tap + 2, (tap + 2) % 3);
            } else if (kc < 7) {
                LOAD_B(kc + 1, tap + 2 - 9, (tap + 2) % 3);
            }
            if (tap == 0 && kc < 7) LOAD_A(kc + 1, (kc + 1) & 1);
            CP_COMMIT();
            const int shift = (tap / 3 - 1) * PW + (tap % 3) - 1;   // compile-time
            COMPUTE(Ab, shift, sbase + 2 * ABYTES + (tap % 3) * BBYTES);
        }
    }

    __syncthreads();
    float* ssc = reinterpret_cast<float*>(smem);
    float* ssh = ssc + 128;
    if (tid < 128) {
        int c = n0 + tid;
        ssc[tid] = g_s1[c];
        ssh[tid] = g_b1[c];
    }
    __syncthreads();

    const int g = lane >> 2, t = lane & 3;
#pragma unroll
    for (int i = 0; i < 4; i++) {
#pragma unroll
        for (int j = 0; j < 8; j++) {
            int cl = wn + 8 * j + 2 * t;
            int ch = n0 + cl;
#pragma unroll
            for (int hf = 0; hf < 2; hf++) {
                int row = p0 + wm + 16 * i + g + hf * 8;
                float v0 = acc[i][j][hf * 2 + 0];
                float v1 = acc[i][j][hf * 2 + 1];
                v0 = fmaf(v0, ssc[cl], ssh[cl]);
                v1 = fmaf(v1, ssc[cl + 1], ssh[cl + 1]);
                v0 = v0 / (1.f + __expf(-v0));
                v1 = v1 / (1.f + __expf(-v1));
                *reinterpret_cast<__half2*>(&g_h[(size_t)row * 512 + ch]) =
                    __floats2half2_rn(v0, v1);
            }
        }
    }
}

// ------------------------------- conv2 (R11 + store trim) -----------------
__global__ void __launch_bounds__(NT, 2)
conv2_mma(const float* __restrict__ bias2) {
    extern __shared__ __align__(128) __half smem[];
    const uint32_t sbase = s2u(smem);
    const int tid = threadIdx.x, lane = tid & 31, warp = tid >> 5;
    const int wm = (warp & 1) * 64;
    const int wn = (warp >> 1) * 64;
    const int n0 = blockIdx.x * 128;
    const int p0 = blockIdx.y * 128;

    float acc[4][8][4];
#pragma unroll
    for (int i = 0; i < 4; i++)
#pragma unroll
        for (int j = 0; j < 8; j++)
#pragma unroll
            for (int k = 0; k < 4; k++) acc[i][j][k] = 0.f;

    auto LOADSTAGE = [&](int s, int slot) {
        uint32_t dstA = sbase + slot * STAGE2;
        uint32_t dstB = dstA + TILE2;
        int kc = s * 64;
        const __half* srcA = g_h + (size_t)p0 * 512 + kc;
        const __half* srcB = g_w2t + (size_t)n0 * 512 + kc;
#pragma unroll
        for (int u = 0; u < 8; u++) {
            int q = tid + u * NT;
            int r = q >> 3, c = q & 7;
            cpa16(dstA + r * 128 + ((c ^ (r & 7)) * 16), srcA + (size_t)r * 512 + c * 8);
        }
#pragma unroll
        for (int u = 0; u < 8; u++) {
            int q = tid + u * NT;
            int r = q >> 3, c = q & 7;
            cpa16(dstB + r * 128 + ((c ^ (r & 7)) * 16), srcB + (size_t)r * 512 + c * 8);
        }
        CP_COMMIT();
    };

    const int rA = wm + (lane & 15);
    const int hiA = lane >> 4;
    const int rB = wn + (lane & 7) + ((lane & 16) >> 1);
    const int hiB = (lane >> 3) & 1;

    auto COMPUTE = [&](int slot) {
        uint32_t Ab = sbase + slot * STAGE2;
        uint32_t Bb = Ab + TILE2;
#pragma unroll
        for (int ks = 0; ks < 4; ks++) {
            uint32_t a[4][4], b[4][4];
#pragma unroll
            for (int i = 0; i < 4; i++) {
                int r = rA + 16 * i;
                LDSM4(a[i], Ab + r * 128 + (((2 * ks + hiA) ^ (r & 7)) * 16));
            }
#pragma unroll
            for (int pr = 0; pr < 4; pr++) {
                int r = rB + 16 * pr;
                LDSM4(b[pr], Bb + r * 128 + (((2 * ks + hiB) ^ (r & 7)) * 16));
            }
#pragma unroll
            for (int i = 0; i < 4; i++)
#pragma unroll
                for (int j = 0; j < 8; j++)
                    MMA16(acc[i][j], a[i], b[j >> 1][(j & 1) * 2], b[j >> 1][(j & 1) * 2 + 1]);
        }
    };

    LOADSTAGE(0, 0);
    LOADSTAGE(1, 1);
#pragma unroll
    for (int s = 0; s < 8; s++) {
        if (s + 2 < 8) CP_WAIT(1); else CP_WAIT(0);
        __syncthreads();
        if (s + 2 < 8) LOADSTAGE(s + 2, (s + 2) % 3);
        COMPUTE(s % 3);
    }

    __syncthreads();
    float* ssh = reinterpret_cast<float*>(smem);
    if (tid < 128) {
        int c = n0 + tid;
        ssh[tid] = (c < COUT) ? bias2[c] : 0.f;
    }
    __syncthreads();

    const int g = lane >> 2, t = lane & 3;
#pragma unroll
    for (int i = 0; i < 4; i++) {
#pragma unroll
        for (int j = 0; j < 8; j++) {
            int cl = wn + 8 * j + 2 * t;
            int ch = n0 + cl;
            if (ch >= 428) continue;        // decode consumes only ch<428
#pragma unroll
            for (int hf = 0; hf < 2; hf++) {
                int row = p0 + wm + 16 * i + g + hf * 8;
                *reinterpret_cast<float2*>(&g_det[(size_t)row * 512 + ch]) =
                    make_float2(acc[i][j][hf * 2 + 0] + ssh[cl],
                                acc[i][j][hf * 2 + 1] + ssh[cl + 1]);
            }
        }
    }
}

// ------------------------------- decode (R13) -----------------------------
__global__ void __launch_bounds__(512)
decode_kernel(const float* __restrict__ anchors, float* __restrict__ out) {
    extern __shared__ float srow[];            // [40][DEC_STRIDE]
    int y = blockIdx.x, b = blockIdx.y;
    int tid = threadIdx.x;

    const float* rowbase = g_det + ((size_t)b * PPI + (size_t)(y + 1) * PW + 1) * 512;
    for (int i = tid; i < 40 * 107; i += 512) {
        int xl = i / 107, q = i - xl * 107;
        *reinterpret_cast<float4*>(&srow[xl * DEC_STRIDE + q * 4]) =
            *reinterpret_cast<const float4*>(rowbase + (size_t)xl * 512 + q * 4);
    }
    __syncthreads();

    int pid = tid >> 1;
    int cpid = pid < 200 ? pid : 199;
    int half = tid & 1;
    int xl = cpid / 5, a = cpid - xl * 5;
    const float* dp = srow + xl * DEC_STRIDE + a * 85;

    float cls[40];
    float mx = -1e30f;
    const float* cp = dp + 5 + half * 40;
#pragma unroll
    for (int c = 0; c < 40; c++) { cls[c] = cp[c]; mx = fmaxf(mx, cls[c]); }
    mx = fmaxf(mx, __shfl_xor_sync(0xFFFFFFFF, mx, 1));
    float sum = 0.f;
#pragma unroll
    for (int c = 0; c < 40; c++) { cls[c] = __expf(cls[c] - mx); sum += cls[c]; }
    sum += __shfl_xor_sync(0xFFFFFFFF, sum, 1);
    float inv = 1.f / sum;

    if (pid < 200) {
        int n = b * 1600 + y * 40 + xl;
        float* co = out + 640000 + (size_t)(n * 5 + a) * 80 + half * 40;
#pragma unroll
        for (int c = 0; c < 40; c += 4)
            *reinterpret_cast<float4*>(&co[c]) = make_float4(cls[c] * inv, cls[c + 1] * inv,
                                                             cls[c + 2] * inv, cls[c + 3] * inv);
        if (half == 0) {
            float d0 = dp[0], d1 = dp[1], d2 = dp[2], d3 = dp[3], d4 = dp[4];
            float bx = ((float)xl + 1.f / (1.f + __expf(-d0))) * (1.f / 40.f);
            float by = ((float)y + 1.f / (1.f + __expf(-d1))) * (1.f / 40.f);
            float bw = __ldg(anchors + 2 * a)     * __expf(d2);
            float bh = __ldg(anchors + 2 * a + 1) * __expf(d3);
            *reinterpret_cast<float4*>(&out[(size_t)(n * 5 + a) * 4]) =
                make_float4(bx, by, bw, bh);
            out[512000 + n * 5 + a] = 1.f / (1.f + __expf(-d4));
        }
    }
}

// ------------------------------- host ------------------------------------
extern "C" void kernel_launch(void* const* d_in, const int* in_sizes, int n_in,
                              void* d_out, int out_size) {
    const float* x       = (const float*)d_in[0];
    const float* w1      = (const float*)d_in[1];
    const float* gamma   = (const float*)d_in[2];
    const float* beta    = (const float*)d_in[3];
    const float* mean    = (const float*)d_in[4];
    const float* var     = (const float*)d_in[5];
    const float* w2      = (const float*)d_in[6];
    const float* b2      = (const float*)d_in[7];
    const float* anchors = (const float*)d_in[8];
    float* out = (float*)d_out;

    cudaFuncSetAttribute(conv1_mma,     cudaFuncAttributeMaxDynamicSharedMemorySize, SMEM1);
    cudaFuncSetAttribute(conv2_mma,     cudaFuncAttributeMaxDynamicSharedMemorySize, SMEM2);
    cudaFuncSetAttribute(decode_kernel, cudaFuncAttributeMaxDynamicSharedMemorySize, SMEM_DEC);

    prep_w<<<289, 256>>>(w1, w2, gamma, beta, mean, var);
    prep_x<<<dim3(8, 42, 16), 256>>>(x);
    conv1_mma<<<dim3(4, MTILES), NT, SMEM1>>>();
    conv2_mma<<<dim3(4, MTILES), NT, SMEM2>>>(b2);
    decode_kernel<<<dim3(40, 16), 512, SMEM_DEC>>>(anchors, out);
}

// round 15
// speedup vs baseline: 1.1040x; 1.0347x over previous
#include <cuda_runtime.h>
#include <cuda_fp16.h>
#include <math.h>
#include <stdint.h>

// RegionOutputLayer via fp16 mma.sync (m16n8k16), compute_100-safe.
// R15: conv1/conv2 = R11 verbatim (422us best; R14's ch<428 trim reverted —
// it pushed regs 236->255 and cost 6us). decode = R13 logic split into
// half-row blocks (grid 1280, 34.9KB smem) for 2x residency.

namespace {
constexpr int COUT = 425;
constexpr int BATCH = 16, HH = 40, WW = 40;
constexpr int PW = 42, PPI = 42 * 42;      // 1764
constexpr int P = BATCH * PPI;             // 28224
constexpr int NSP = BATCH * HH * WW;       // 25600
constexpr int GPRE = 64;
constexpr int PROWS = GPRE + P + 128;      // 28416
constexpr int MTILES = 221;
constexpr int MROWS = MTILES * 128;        // 28288

constexpr int HALO = 216;                  // 128 + 2*44 pad
constexpr int ABYTES = HALO * 128;         // 27648
constexpr int ACH = HALO * 8;              // 1728 16B chunks
constexpr int BBYTES = 16384;
constexpr int SMEM1 = 2 * ABYTES + 3 * BBYTES;   // 104448

constexpr int TILE2 = 16384;
constexpr int STAGE2 = 2 * TILE2;
constexpr int SMEM2 = 3 * STAGE2;          // 98304

constexpr int DEC_STRIDE = 436;
constexpr int SMEM_DEC = 20 * DEC_STRIDE * 4;    // 34880 (half-row)

constexpr int NT = 128;                    // 4 warps
}

__device__ __align__(128) __half g_xp[(size_t)PROWS * 512];
__device__ __align__(128) __half g_h [(size_t)MROWS * 512];
__device__ __align__(128) __half g_w1t[9 * 512 * 512];   // [tap][cout][cin]
__device__ __align__(128) __half g_w2t[512 * 512];
__device__ __align__(128) float  g_det[(size_t)MROWS * 512];
__device__ float g_s1[512], g_b1[512];

static __device__ __forceinline__ uint32_t s2u(const void* p) {
    uint32_t a;
    asm("{ .reg .u64 t; cvta.to.shared.u64 t, %1; cvt.u32.u64 %0, t; }" : "=r"(a) : "l"(p));
    return a;
}
static __device__ __forceinline__ void cpa16(uint32_t dst, const void* src) {
    asm volatile("cp.async.cg.shared.global [%0], [%1], 16;"
                 :: "r"(dst), "l"(__cvta_generic_to_global(src)));
}
#define CP_COMMIT() asm volatile("cp.async.commit_group;" ::: "memory")
#define CP_WAIT(n)  asm volatile("cp.async.wait_group %0;" :: "n"(n) : "memory")
#define LDSM4(r, a) \
    asm volatile("ldmatrix.sync.aligned.m8n8.x4.shared.b16 {%0,%1,%2,%3}, [%4];" \
                 : "=r"((r)[0]), "=r"((r)[1]), "=r"((r)[2]), "=r"((r)[3]) : "r"(a))
#define MMA16(c, a, b0, b1) \
    asm volatile("mma.sync.aligned.m16n8k16.row.col.f32.f16.f16.f32 " \
                 "{%0,%1,%2,%3},{%4,%5,%6,%7},{%8,%9},{%0,%1,%2,%3};" \
                 : "+f"((c)[0]), "+f"((c)[1]), "+f"((c)[2]), "+f"((c)[3]) \
                 : "r"((a)[0]), "r"((a)[1]), "r"((a)[2]), "r"((a)[3]), "r"(b0), "r"(b1))

// ------------------------------- prep ------------------------------------
__global__ void prep_w(const float* __restrict__ w1, const float* __restrict__ w2,
                       const float* __restrict__ gamma, const float* __restrict__ beta,
                       const float* __restrict__ mean, const float* __restrict__ var) {
    int blk = blockIdx.x;
    if (blk < 256) {                        // w1 transpose, both sides coalesced
        __shared__ float s[9216];
        int r0 = blk * 1024;
        const float* src = w1 + (size_t)r0 * 9;
        for (int i = threadIdx.x; i < 9216; i += 256) s[i] = src[i];
        __syncthreads();
#pragma unroll
        for (int t = 0; t < 9; t++)
            for (int i = threadIdx.x; i < 1024; i += 256)
                g_w1t[(size_t)t * 262144 + r0 + i] = __float2half_rn(s[i * 9 + t]);
    } else if (blk < 288) {
        int base = (blk - 256) * 8192;
        for (int i = threadIdx.x; i < 8192; i += 256) {
            int idx = base + i;
            int co = idx >> 9, ci = idx & 511;
            g_w2t[idx] = __float2half_rn(co < COUT ? w2[co * 512 + ci] : 0.f);
        }
    } else {
        for (int i = threadIdx.x; i < 512; i += 256) {
            float s = gamma[i] * rsqrtf(var[i] + 1e-5f);
            g_s1[i] = s;
            g_b1[i] = beta[i] - mean[i] * s;
        }
    }
}

__global__ void prep_x(const float* __restrict__ x) {
    __shared__ float s[64][41];
    int c0 = blockIdx.x * 64, yp = blockIdx.y, b = blockIdx.z;
    int tid = threadIdx.x;
    int y = yp - 1;
    bool interior = (y >= 0 && y < HH);
    if (interior)
        for (int i = tid; i < 64 * 40; i += 256) {
            int c = i / 40, xx = i % 40;
            s[c][xx] = x[(((size_t)b * 512 + c0 + c) * HH + y) * WW + xx];
        }
    __syncthreads();
    size_t pbase = (size_t)GPRE + (size_t)b * PPI + (size_t)yp * PW;
    for (int i = tid; i < 42 * 64; i += 256) {
        int xp = i >> 6, c = i & 63;
        float v = (interior && xp >= 1 && xp <= 40) ? s[c][xp - 1] : 0.f;
        g_xp[(pbase + xp) * 512 + c0 + c] = __float2half_rn(v);
    }
}

// ------------------------------- conv1 (R11) ------------------------------
__global__ void __launch_bounds__(NT, 2)
conv1_mma() {
    extern __shared__ __align__(128) __half smem[];
    const uint32_t sbase = s2u(smem);
    const int tid = threadIdx.x, lane = tid & 31, warp = tid >> 5;
    const int wm = (warp & 1) * 64;
    const int wn = (warp >> 1) * 64;
    const int n0 = blockIdx.x * 128;
    const int p0 = blockIdx.y * 128;

    float acc[4][8][4];
#pragma unroll
    for (int i = 0; i < 4; i++)
#pragma unroll
        for (int j = 0; j < 8; j++)
#pragma unroll
            for (int k = 0; k < 4; k++) acc[i][j][k] = 0.f;

    const __half* Abase = g_xp + (size_t)(GPRE + p0 - 44) * 512;

    auto LOAD_A = [&](int kc, int slot) {
        const __half* src = Abase + kc * 64;
        uint32_t dst = sbase + slot * ABYTES;
#pragma unroll
        for (int u = 0; u < 14; u++) {
            int id = tid + u * NT;
            if (id < ACH) {
                int r = id >> 3, c = id & 7;
                cpa16(dst + r * 128 + ((c ^ (r & 7)) * 16), src + (size_t)r * 512 + c * 8);
            }
        }
    };
    auto LOAD_B = [&](int kc, int tap, int slot) {
        const __half* src = g_w1t + ((size_t)tap * 512 + n0) * 512 + kc * 64;
        uint32_t dst = sbase + 2 * ABYTES + slot * BBYTES;
#pragma unroll
        for (int u = 0; u < 8; u++) {
            int id = tid + u * NT;
            int r = id >> 3, c = id & 7;
            cpa16(dst + r * 128 + ((c ^ (r & 7)) * 16), src + (size_t)r * 512 + c * 8);
        }
    };

    const int rA_base = wm + (lane & 15) + 44;
    const int hiA = lane >> 4;
    const int rB = wn + (lane & 7) + ((lane & 16) >> 1);
    const int hiB = (lane >> 3) & 1;

    auto COMPUTE = [&](uint32_t Ab, int shift, uint32_t Bb) {
#pragma unroll
        for (int ks = 0; ks < 4; ks++) {
            uint32_t a[4][4], b[4][4];
#pragma unroll
            for (int i = 0; i < 4; i++) {
                int r = rA_base + 16 * i + shift;
                LDSM4(a[i], Ab + r * 128 + (((2 * ks + hiA) ^ (r & 7)) * 16));
            }
#pragma unroll
            for (int pr = 0; pr < 4; pr++) {
                int r = rB + 16 * pr;
                LDSM4(b[pr], Bb + r * 128 + (((2 * ks + hiB) ^ (r & 7)) * 16));
            }
#pragma unroll
            for (int i = 0; i < 4; i++)
#pragma unroll
                for (int j = 0; j < 8; j++)
                    MMA16(acc[i][j], a[i], b[j >> 1][(j & 1) * 2], b[j >> 1][(j & 1) * 2 + 1]);
        }
    };

    LOAD_A(0, 0); LOAD_B(0, 0, 0); CP_COMMIT();
    LOAD_B(0, 1, 1); CP_COMMIT();

    for (int kc = 0; kc < 8; kc++) {
        const uint32_t Ab = sbase + (kc & 1) * ABYTES;
#pragma unroll
        for (int tap = 0; tap < 9; tap++) {
            CP_WAIT(1);
            __syncthreads();
            if (tap + 2 < 9) {
                LOAD_B(kc, tap + 2, (tap + 2) % 3);
            } else if (kc < 7) {
                LOAD_B(kc + 1, tap + 2 - 9, (tap + 2) % 3);
            }
            if (tap == 0 && kc < 7) LOAD_A(kc + 1, (kc + 1) & 1);
            CP_COMMIT();
            const int shift = (tap / 3 - 1) * PW + (tap % 3) - 1;   // compile-time
            COMPUTE(Ab, shift, sbase + 2 * ABYTES + (tap % 3) * BBYTES);
        }
    }

    __syncthreads();
    float* ssc = reinterpret_cast<float*>(smem);
    float* ssh = ssc + 128;
    if (tid < 128) {
        int c = n0 + tid;
        ssc[tid] = g_s1[c];
        ssh[tid] = g_b1[c];
    }
    __syncthreads();

    const int g = lane >> 2, t = lane & 3;
#pragma unroll
    for (int i = 0; i < 4; i++) {
#pragma unroll
        for (int j = 0; j < 8; j++) {
            int cl = wn + 8 * j + 2 * t;
            int ch = n0 + cl;
#pragma unroll
            for (int hf = 0; hf < 2; hf++) {
                int row = p0 + wm + 16 * i + g + hf * 8;
                float v0 = acc[i][j][hf * 2 + 0];
                float v1 = acc[i][j][hf * 2 + 1];
                v0 = fmaf(v0, ssc[cl], ssh[cl]);
                v1 = fmaf(v1, ssc[cl + 1], ssh[cl + 1]);
                v0 = v0 / (1.f + __expf(-v0));
                v1 = v1 / (1.f + __expf(-v1));
                *reinterpret_cast<__half2*>(&g_h[(size_t)row * 512 + ch]) =
                    __floats2half2_rn(v0, v1);
            }
        }
    }
}

// ------------------------------- conv2 (R11) ------------------------------
__global__ void __launch_bounds__(NT, 2)
conv2_mma(const float* __restrict__ bias2) {
    extern __shared__ __align__(128) __half smem[];
    const uint32_t sbase = s2u(smem);
    const int tid = threadIdx.x, lane = tid & 31, warp = tid >> 5;
    const int wm = (warp & 1) * 64;
    const int wn = (warp >> 1) * 64;
    const int n0 = blockIdx.x * 128;
    const int p0 = blockIdx.y * 128;

    float acc[4][8][4];
#pragma unroll
    for (int i = 0; i < 4; i++)
#pragma unroll
        for (int j = 0; j < 8; j++)
#pragma unroll
            for (int k = 0; k < 4; k++) acc[i][j][k] = 0.f;

    auto LOADSTAGE = [&](int s, int slot) {
        uint32_t dstA = sbase + slot * STAGE2;
        uint32_t dstB = dstA + TILE2;
        int kc = s * 64;
        const __half* srcA = g_h + (size_t)p0 * 512 + kc;
        const __half* srcB = g_w2t + (size_t)n0 * 512 + kc;
#pragma unroll
        for (int u = 0; u < 8; u++) {
            int q = tid + u * NT;
            int r = q >> 3, c = q & 7;
            cpa16(dstA + r * 128 + ((c ^ (r & 7)) * 16), srcA + (size_t)r * 512 + c * 8);
        }
#pragma unroll
        for (int u = 0; u < 8; u++) {
            int q = tid + u * NT;
            int r = q >> 3, c = q & 7;
            cpa16(dstB + r * 128 + ((c ^ (r & 7)) * 16), srcB + (size_t)r * 512 + c * 8);
        }
        CP_COMMIT();
    };

    const int rA = wm + (lane & 15);
    const int hiA = lane >> 4;
    const int rB = wn + (lane & 7) + ((lane & 16) >> 1);
    const int hiB = (lane >> 3) & 1;

    auto COMPUTE = [&](int slot) {
        uint32_t Ab = sbase + slot * STAGE2;
        uint32_t Bb = Ab + TILE2;
#pragma unroll
        for (int ks = 0; ks < 4; ks++) {
            uint32_t a[4][4], b[4][4];
#pragma unroll
            for (int i = 0; i < 4; i++) {
                int r = rA + 16 * i;
                LDSM4(a[i], Ab + r * 128 + (((2 * ks + hiA) ^ (r & 7)) * 16));
            }
#pragma unroll
            for (int pr = 0; pr < 4; pr++) {
                int r = rB + 16 * pr;
                LDSM4(b[pr], Bb + r * 128 + (((2 * ks + hiB) ^ (r & 7)) * 16));
            }
#pragma unroll
            for (int i = 0; i < 4; i++)
#pragma unroll
                for (int j = 0; j < 8; j++)
                    MMA16(acc[i][j], a[i], b[j >> 1][(j & 1) * 2], b[j >> 1][(j & 1) * 2 + 1]);
        }
    };

    LOADSTAGE(0, 0);
    LOADSTAGE(1, 1);
#pragma unroll
    for (int s = 0; s < 8; s++) {
        if (s + 2 < 8) CP_WAIT(1); else CP_WAIT(0);
        __syncthreads();
        if (s + 2 < 8) LOADSTAGE(s + 2, (s + 2) % 3);
        COMPUTE(s % 3);
    }

    __syncthreads();
    float* ssh = reinterpret_cast<float*>(smem);
    if (tid < 128) {
        int c = n0 + tid;
        ssh[tid] = (c < COUT) ? bias2[c] : 0.f;
    }
    __syncthreads();

    const int g = lane >> 2, t = lane & 3;
#pragma unroll
    for (int i = 0; i < 4; i++) {
#pragma unroll
        for (int j = 0; j < 8; j++) {
            int cl = wn + 8 * j + 2 * t;
            int ch = n0 + cl;
#pragma unroll
            for (int hf = 0; hf < 2; hf++) {
                int row = p0 + wm + 16 * i + g + hf * 8;
                *reinterpret_cast<float2*>(&g_det[(size_t)row * 512 + ch]) =
                    make_float2(acc[i][j][hf * 2 + 0] + ssh[cl],
                                acc[i][j][hf * 2 + 1] + ssh[cl + 1]);
            }
        }
    }
}

// ------------------------------- decode (half-row) ------------------------
__global__ void __launch_bounds__(256)
decode_kernel(const float* __restrict__ anchors, float* __restrict__ out) {
    extern __shared__ float srow[];            // [20][DEC_STRIDE]
    int hy = blockIdx.x;                       // half-row index
    int y = hy >> 1;
    int xbase = (hy & 1) * 20;
    int b = blockIdx.y;
    int tid = threadIdx.x;

    const float* rowbase = g_det + ((size_t)b * PPI + (size_t)(y + 1) * PW + 1 + xbase) * 512;
    for (int i = tid; i < 20 * 107; i += 256) {
        int xl = i / 107, q = i - xl * 107;
        *reinterpret_cast<float4*>(&srow[xl * DEC_STRIDE + q * 4]) =
            *reinterpret_cast<const float4*>(rowbase + (size_t)xl * 512 + q * 4);
    }
    __syncthreads();

    // 2 threads per (x, anchor): 100 pids x 2 halves = 200 active threads.
    int pid = tid >> 1;
    int cpid = pid < 100 ? pid : 99;
    int half = tid & 1;
    int xl = cpid / 5, a = cpid - xl * 5;
    const float* dp = srow + xl * DEC_STRIDE + a * 85;

    float cls[40];
    float mx = -1e30f;
    const float* cp = dp + 5 + half * 40;
#pragma unroll
    for (int c = 0; c < 40; c++) { cls[c] = cp[c]; mx = fmaxf(mx, cls[c]); }
    mx = fmaxf(mx, __shfl_xor_sync(0xFFFFFFFF, mx, 1));
    float sum = 0.f;
#pragma unroll
    for (int c = 0; c < 40; c++) { cls[c] = __expf(cls[c] - mx); sum += cls[c]; }
    sum += __shfl_xor_sync(0xFFFFFFFF, sum, 1);
    float inv = 1.f / sum;

    if (pid < 100) {
        int xg = xbase + xl;
        int n = b * 1600 + y * 40 + xg;
        float* co = out + 640000 + (size_t)(n * 5 + a) * 80 + half * 40;
#pragma unroll
        for (int c = 0; c < 40; c += 4)
            *reinterpret_cast<float4*>(&co[c]) = make_float4(cls[c] * inv, cls[c + 1] * inv,
                                                             cls[c + 2] * inv, cls[c + 3] * inv);
        if (half == 0) {
            float d0 = dp[0], d1 = dp[1], d2 = dp[2], d3 = dp[3], d4 = dp[4];
            float bx = ((float)xg + 1.f / (1.f + __expf(-d0))) * (1.f / 40.f);
            float by = ((float)y + 1.f / (1.f + __expf(-d1))) * (1.f / 40.f);
            float bw = __ldg(anchors + 2 * a)     * __expf(d2);
            float bh = __ldg(anchors + 2 * a + 1) * __expf(d3);
            *reinterpret_cast<float4*>(&out[(size_t)(n * 5 + a) * 4]) =
                make_float4(bx, by, bw, bh);
            out[512000 + n * 5 + a] = 1.f / (1.f + __expf(-d4));
        }
    }
}

// ------------------------------- host ------------------------------------
extern "C" void kernel_launch(void* const* d_in, const int* in_sizes, int n_in,
                              void* d_out, int out_size) {
    const float* x       = (const float*)d_in[0];
    const float* w1      = (const float*)d_in[1];
    const float* gamma   = (const float*)d_in[2];
    const float* beta    = (const float*)d_in[3];
    const float* mean    = (const float*)d_in[4];
    const float* var     = (const float*)d_in[5];
    const float* w2      = (const float*)d_in[6];
    const float* b2      = (const float*)d_in[7];
    const float* anchors = (const float*)d_in[8];
    float* out = (float*)d_out;

    cudaFuncSetAttribute(conv1_mma,     cudaFuncAttributeMaxDynamicSharedMemorySize, SMEM1);
    cudaFuncSetAttribute(conv2_mma,     cudaFuncAttributeMaxDynamicSharedMemorySize, SMEM2);
    cudaFuncSetAttribute(decode_kernel, cudaFuncAttributeMaxDynamicSharedMemorySize, SMEM_DEC);

    prep_w<<<289, 256>>>(w1, w2, gamma, beta, mean, var);
    prep_x<<<dim3(8, 42, 16), 256>>>(x);
    conv1_mma<<<dim3(4, MTILES), NT, SMEM1>>>();
    conv2_mma<<<dim3(4, MTILES), NT, SMEM2>>>(b2);
    decode_kernel<<<dim3(80, 16), 256, SMEM_DEC>>>(anchors, out);
}